// round 14
// baseline (speedup 1.0000x reference)
#include <cuda_runtime.h>
#include <cuda_bf16.h>
#include <math.h>

// ---------------------------------------------------------------------------
// PatchQuantumGenerator — single fused kernel.
//   * circuit after RY-embedding = fixed 32x32 unitary U_g per generator
//   * embedded state is a real product state s[j]
//   * p0/max(p0) == probs[:16]/max(probs[:16])
// => out[b, g*16+i] = |y_i|^2 / max_i |y_i|^2,  y = U_g[0:16,:] @ s(b)
// Block (gsel, tile): tile==0 builds U_gsel in-block then consumes tile 0;
// other tiles overlap their prologue with the build and spin on a
// monotonic per-generator epoch flag (graph-replay safe).
// Main GEMM body = R12 proven config: f32x2 FMA, 2 elems/thread, h=2 split.
// ---------------------------------------------------------------------------

#define NQ 5
#define DIM 32
#define NOUT 16
#define G 4
#define L 4
#define NGATES (L * NQ)

// W layout per row j: [Re(0..7), Im(0..7), Re(8..15), Im(8..15)]
__device__ float g_W[G][DIM][2 * NOUT];
__device__ unsigned g_done[G];   // monotonic: +1 per generator per execution
__device__ unsigned g_tick[G];   // monotonic consumer tickets

typedef unsigned long long ull;

__device__ __forceinline__ ull ffma2(ull a, ull b, ull c) {
    ull d;
    asm("fma.rn.f32x2 %0, %1, %2, %3;" : "=l"(d) : "l"(a), "l"(b), "l"(c));
    return d;
}
__device__ __forceinline__ ull fmul2(ull a, ull b) {
    ull d;
    asm("mul.rn.f32x2 %0, %1, %2;" : "=l"(d) : "l"(a), "l"(b));
    return d;
}
__device__ __forceinline__ ull packab(float lo, float hi) {
    ull r;
    asm("mov.b64 %0, {%1, %2};" : "=l"(r) : "f"(lo), "f"(hi));
    return r;
}
__device__ __forceinline__ ull pack2(float x) {
    ull r;
    asm("mov.b64 %0, {%1, %1};" : "=l"(r) : "f"(x));
    return r;
}
__device__ __forceinline__ float2 unpack2(ull a) {
    float lo, hi;
    asm("mov.b64 {%0, %1}, %2;" : "=f"(lo), "=f"(hi) : "l"(a));
    return make_float2(lo, hi);
}

__global__ void __launch_bounds__(128, 6)
qgen_fused_kernel(const float* __restrict__ x, const float* __restrict__ w,
                  float* __restrict__ out, int B) {
    __shared__ float2 S[DIM][DIM];       // builder state, 8KB (tile==0 only)
    __shared__ float  gm[NGATES][8];     // builder gate matrices
    __shared__ float  Wsh[DIM][2 * NOUT];// 4 KB GEMM operand

    const int gsel = blockIdx.x & 3;
    const int tile = blockIdx.x >> 2;
    const int tid  = threadIdx.x;

    // =======================================================================
    // Builder path: tile 0 builds U_gsel with 128 threads.
    // thread = (col = tid>>2, pbase = tid&3); pairs p = pbase + 4k, k<4.
    // 4 threads per column live in one warp -> per-gate __syncwarp.
    // =======================================================================
    if (tile == 0) {
        const int col   = tid >> 2;      // 0..31
        const int pbase = tid & 3;       // 0..3

        if (tid < NGATES) {
            const int l = tid / NQ, q = tid % NQ;
            const float phi   = w[((gsel * L + l) * NQ + q) * 3 + 0];
            const float theta = w[((gsel * L + l) * NQ + q) * 3 + 1];
            const float omega = w[((gsel * L + l) * NQ + q) * 3 + 2];
            const float c = cosf(0.5f * theta);
            const float s = sinf(0.5f * theta);
            float epx, epy, emx, emy;
            sincosf(-0.5f * (phi + omega), &epy, &epx);  // ep
            sincosf(-0.5f * (phi - omega), &emy, &emx);  // em
            gm[tid][0] = epx * c;   gm[tid][1] = epy * c;     // m00
            gm[tid][2] = -emx * s;  gm[tid][3] = emy * s;     // m01
            gm[tid][4] = emx * s;   gm[tid][5] = emy * s;     // m10
            gm[tid][6] = epx * c;   gm[tid][7] = -epy * c;    // m11
        }
        // init: column col = basis state col; this thread inits i = pbase+4k (8 amps)
        #pragma unroll
        for (int i = pbase; i < DIM; i += 4)
            S[col][i] = make_float2(i == col ? 1.0f : 0.0f, 0.0f);
        __syncthreads();

        float2* a = S[col];
        for (int l = 0; l < L; ++l) {
            for (int q = 0; q < NQ; ++q) {
                const float* m = gm[l * NQ + q];
                const int msk = 1 << (4 - q);
                #pragma unroll
                for (int k = 0; k < 4; ++k) {
                    const int p  = pbase + 4 * k;
                    const int lo = p & (msk - 1);
                    const int i0 = ((p & ~(msk - 1)) << 1) | lo;
                    const int i1 = i0 | msk;
                    const float2 a0 = a[i0], a1 = a[i1];
                    float2 n0, n1;
                    n0.x = m[0] * a0.x - m[1] * a0.y + m[2] * a1.x - m[3] * a1.y;
                    n0.y = m[0] * a0.y + m[1] * a0.x + m[2] * a1.y + m[3] * a1.x;
                    n1.x = m[4] * a0.x - m[5] * a0.y + m[6] * a1.x - m[7] * a1.y;
                    n1.y = m[4] * a0.y + m[5] * a0.x + m[6] * a1.y + m[7] * a1.x;
                    a[i0] = n0;
                    a[i1] = n1;
                }
                __syncwarp();
            }
            const int r = (l % (NQ - 1)) + 1;
            for (int q = 0; q < NQ; ++q) {
                const int cm = 1 << (4 - q);
                const int tq = (q + r) % NQ;
                const int tm = 1 << (4 - tq);
                #pragma unroll
                for (int k = 0; k < 4; ++k) {
                    const int p  = pbase + 4 * k;
                    const int lo = p & (tm - 1);
                    const int i0 = ((p & ~(tm - 1)) << 1) | lo;  // target bit 0
                    if (i0 & cm) {
                        const int i1 = i0 | tm;
                        const float2 tmp = a[i0];
                        a[i0] = a[i1];
                        a[i1] = tmp;
                    }
                }
                __syncwarp();
            }
        }

        // write rows 0..15: row i -> group i>>3: [Re(8h..) at h*16, Im at h*16+8]
        #pragma unroll
        for (int k = 0; k < 4; ++k) {
            const int p = pbase + 4 * k;   // 0..15
            const int h  = p >> 3;
            const int i7 = p & 7;
            g_W[gsel][col][h * 16 + i7]     = a[p].x;
            g_W[gsel][col][h * 16 + 8 + i7] = a[p].y;
        }
        __threadfence();
        __syncthreads();
        if (tid == 0) atomicAdd(&g_done[gsel], 1u);   // release epoch
    }

    // =======================================================================
    // Consumer path (all blocks, incl. tile 0 which just built its own W).
    // =======================================================================
    const int h   = tid & 1;          // column half
    const int idx = tid >> 1;         // 0..63
    const int b0r = tile * 128 + idx;
    const int b1r = b0r + 64;
    const int b0 = min(b0r, B - 1);
    const int b1 = min(b1r, B - 1);

    // ---- prologue: packed (elem0, elem1) product-state prefix (overlaps build)
    ull p3p[8], c3p, s3p, c4p, s4p;
    {
        float cc0[NQ], ss0[NQ], cc1[NQ], ss1[NQ];
        #pragma unroll
        for (int q = 0; q < NQ; ++q) {
            __sincosf(0.5f * x[b0 * NQ + q], &ss0[q], &cc0[q]);
            __sincosf(0.5f * x[b1 * NQ + q], &ss1[q], &cc1[q]);
        }
        ull f0c = packab(cc0[0], cc1[0]), f0s = packab(ss0[0], ss1[0]);
        ull f1c = packab(cc0[1], cc1[1]), f1s = packab(ss0[1], ss1[1]);
        ull f2c = packab(cc0[2], cc1[2]), f2s = packab(ss0[2], ss1[2]);
        c3p = packab(cc0[3], cc1[3]);  s3p = packab(ss0[3], ss1[3]);
        c4p = packab(cc0[4], cc1[4]);  s4p = packab(ss0[4], ss1[4]);
        ull p2p[4];
        p2p[0] = fmul2(f0c, f1c); p2p[1] = fmul2(f0c, f1s);
        p2p[2] = fmul2(f0s, f1c); p2p[3] = fmul2(f0s, f1s);
        #pragma unroll
        for (int k = 0; k < 4; ++k) {
            p3p[2 * k + 0] = fmul2(p2p[k], f2c);
            p3p[2 * k + 1] = fmul2(p2p[k], f2s);
        }
    }

    // ---- wait for this generator's W (epoch flag; replay-safe) ----
    if (tile != 0) {
        if (tid == 0) {
            const unsigned consumers = (gridDim.x >> 2) - 1u;  // per gsel per exec
            const unsigned t = atomicAdd(&g_tick[gsel], 1u);
            const unsigned r = t / consumers;                  // execution index
            while (atomicAdd(&g_done[gsel], 0u) <= r) __nanosleep(64);
            __threadfence();                                   // acquire
        }
        __syncthreads();
    }
    // stage W: 4 KB = 256 float4; 128 threads -> 2 each
    {
        const float4* src = reinterpret_cast<const float4*>(&g_W[gsel][0][0]);
        float4* dst = reinterpret_cast<float4*>(&Wsh[0][0]);
        dst[tid]       = src[tid];
        dst[tid + 128] = src[tid + 128];
    }
    __syncthreads();

    // ---- GEMM: acc[k] packs cols (2k,2k+1) of this half; k<4 Re, k>=4 Im ----
    ull a0[8], a1[8];
    #pragma unroll
    for (int k = 0; k < 8; ++k) { a0[k] = 0ULL; a1[k] = 0ULL; }

    const int hoff = h * 16;

    #pragma unroll
    for (int j4 = 0; j4 < 16; ++j4) {
        const ull p4p = fmul2(p3p[j4 >> 1], (j4 & 1) ? s3p : c3p);
        const float2 vA = unpack2(fmul2(p4p, c4p));
        const float2 vB = unpack2(fmul2(p4p, s4p));
        const ull sA0 = pack2(vA.x), sA1 = pack2(vA.y);
        const ull sB0 = pack2(vB.x), sB1 = pack2(vB.y);
        const ulonglong2* rA = reinterpret_cast<const ulonglong2*>(&Wsh[2 * j4][hoff]);
        const ulonglong2* rB = reinterpret_cast<const ulonglong2*>(&Wsh[2 * j4 + 1][hoff]);
        {
            const ulonglong2 w0 = rA[0], w1 = rA[1], w2 = rA[2], w3 = rA[3];
            a0[0] = ffma2(w0.x, sA0, a0[0]); a0[1] = ffma2(w0.y, sA0, a0[1]);
            a0[2] = ffma2(w1.x, sA0, a0[2]); a0[3] = ffma2(w1.y, sA0, a0[3]);
            a0[4] = ffma2(w2.x, sA0, a0[4]); a0[5] = ffma2(w2.y, sA0, a0[5]);
            a0[6] = ffma2(w3.x, sA0, a0[6]); a0[7] = ffma2(w3.y, sA0, a0[7]);
            a1[0] = ffma2(w0.x, sA1, a1[0]); a1[1] = ffma2(w0.y, sA1, a1[1]);
            a1[2] = ffma2(w1.x, sA1, a1[2]); a1[3] = ffma2(w1.y, sA1, a1[3]);
            a1[4] = ffma2(w2.x, sA1, a1[4]); a1[5] = ffma2(w2.y, sA1, a1[5]);
            a1[6] = ffma2(w3.x, sA1, a1[6]); a1[7] = ffma2(w3.y, sA1, a1[7]);
        }
        {
            const ulonglong2 w0 = rB[0], w1 = rB[1], w2 = rB[2], w3 = rB[3];
            a0[0] = ffma2(w0.x, sB0, a0[0]); a0[1] = ffma2(w0.y, sB0, a0[1]);
            a0[2] = ffma2(w1.x, sB0, a0[2]); a0[3] = ffma2(w1.y, sB0, a0[3]);
            a0[4] = ffma2(w2.x, sB0, a0[4]); a0[5] = ffma2(w2.y, sB0, a0[5]);
            a0[6] = ffma2(w3.x, sB0, a0[6]); a0[7] = ffma2(w3.y, sB0, a0[7]);
            a1[0] = ffma2(w0.x, sB1, a1[0]); a1[1] = ffma2(w0.y, sB1, a1[1]);
            a1[2] = ffma2(w1.x, sB1, a1[2]); a1[3] = ffma2(w1.y, sB1, a1[3]);
            a1[4] = ffma2(w2.x, sB1, a1[4]); a1[5] = ffma2(w2.y, sB1, a1[5]);
            a1[6] = ffma2(w3.x, sB1, a1[6]); a1[7] = ffma2(w3.y, sB1, a1[7]);
        }
    }

    // ---- epilogue: outputs 8h..8h+7 per element; max via shfl.xor(1) ----
    #pragma unroll
    for (int e = 0; e < 2; ++e) {
        const ull* a = e ? a1 : a0;
        const int br = e ? b1r : b0r;
        float pr[8];
        float mx = 0.0f;
        #pragma unroll
        for (int k = 0; k < 4; ++k) {
            const float2 re = unpack2(a[k]);
            const float2 im = unpack2(a[4 + k]);
            pr[2 * k + 0] = re.x * re.x + im.x * im.x;
            pr[2 * k + 1] = re.y * re.y + im.y * im.y;
            mx = fmaxf(mx, fmaxf(pr[2 * k], pr[2 * k + 1]));
        }
        mx = fmaxf(mx, __shfl_xor_sync(0xffffffffu, mx, 1));
        const float inv = 1.0f / mx;
        if (br < B) {
            float4* ov = reinterpret_cast<float4*>(out + (size_t)br * (G * NOUT) + gsel * NOUT + 8 * h);
            #pragma unroll
            for (int i4 = 0; i4 < 2; ++i4) {
                float4 o;
                o.x = pr[i4 * 4 + 0] * inv;
                o.y = pr[i4 * 4 + 1] * inv;
                o.z = pr[i4 * 4 + 2] * inv;
                o.w = pr[i4 * 4 + 3] * inv;
                ov[i4] = o;
            }
        }
    }
}

extern "C" void kernel_launch(void* const* d_in, const int* in_sizes, int n_in,
                              void* d_out, int out_size) {
    const float* x = (const float*)d_in[0];        // [B, 5]
    const float* w = (const float*)d_in[1];        // [4, 4, 5, 3]
    float* out = (float*)d_out;                    // [B, 64]
    const int B = in_sizes[0] / NQ;

    const int tiles = (B + 127) / 128;             // 128 elements per tile
    qgen_fused_kernel<<<tiles * G, 128>>>(x, w, out, B);
}

// round 15
// speedup vs baseline: 1.0538x; 1.0538x over previous
#include <cuda_runtime.h>
#include <cuda_bf16.h>
#include <math.h>

// ---------------------------------------------------------------------------
// PatchQuantumGenerator — single fused kernel (fixed R14).
//   * circuit after RY-embedding = fixed 32x32 unitary U_g per generator
//   * embedded state is a real product state s[j]
//   * p0/max(p0) == probs[:16]/max(probs[:16])
// => out[b, g*16+i] = |y_i|^2 / max_i |y_i|^2,  y = U_g[0:16,:] @ s(b)
// Block (gsel, tile): tile==0 builds U_gsel in-block; other tiles overlap
// their prologue with the build, then spin on a monotonic per-generator
// epoch flag via PLAIN VOLATILE LOADS (no atomic-RMW polling).
// launch_bounds(128,5): 96-reg headroom so the fused kernel cannot spill.
// GEMM body = R12 proven config: f32x2 FMA, 2 elems/thread, h=2 split.
// ---------------------------------------------------------------------------

#define NQ 5
#define DIM 32
#define NOUT 16
#define G 4
#define L 4
#define NGATES (L * NQ)

// W layout per row j: [Re(0..7), Im(0..7), Re(8..15), Im(8..15)]
__device__ float g_W[G][DIM][2 * NOUT];
__device__ volatile unsigned g_done[G];  // monotonic: +1 per generator per execution
__device__ unsigned g_tick[G];           // monotonic consumer tickets

typedef unsigned long long ull;

__device__ __forceinline__ ull ffma2(ull a, ull b, ull c) {
    ull d;
    asm("fma.rn.f32x2 %0, %1, %2, %3;" : "=l"(d) : "l"(a), "l"(b), "l"(c));
    return d;
}
__device__ __forceinline__ ull fmul2(ull a, ull b) {
    ull d;
    asm("mul.rn.f32x2 %0, %1, %2;" : "=l"(d) : "l"(a), "l"(b));
    return d;
}
__device__ __forceinline__ ull packab(float lo, float hi) {
    ull r;
    asm("mov.b64 %0, {%1, %2};" : "=l"(r) : "f"(lo), "f"(hi));
    return r;
}
__device__ __forceinline__ ull pack2(float x) {
    ull r;
    asm("mov.b64 %0, {%1, %1};" : "=l"(r) : "f"(x));
    return r;
}
__device__ __forceinline__ float2 unpack2(ull a) {
    float lo, hi;
    asm("mov.b64 {%0, %1}, %2;" : "=f"(lo), "=f"(hi) : "l"(a));
    return make_float2(lo, hi);
}

__global__ void __launch_bounds__(128, 5)
qgen_fused_kernel(const float* __restrict__ x, const float* __restrict__ w,
                  float* __restrict__ out, int B) {
    __shared__ float2 S[DIM][DIM];       // builder state, 8KB (tile==0 only)
    __shared__ float  gm[NGATES][8];     // builder gate matrices
    __shared__ float  Wsh[DIM][2 * NOUT];// 4 KB GEMM operand

    const int gsel = blockIdx.x & 3;
    const int tile = blockIdx.x >> 2;
    const int tid  = threadIdx.x;

    // =======================================================================
    // Builder path: tile 0 builds U_gsel with 128 threads.
    // thread = (col = tid>>2, pbase = tid&3); pairs p = pbase + 4k, k<4.
    // 4 threads per column live in one warp -> per-gate __syncwarp.
    // =======================================================================
    if (tile == 0) {
        const int col   = tid >> 2;      // 0..31
        const int pbase = tid & 3;       // 0..3

        if (tid < NGATES) {
            const int l = tid / NQ, q = tid % NQ;
            const float phi   = w[((gsel * L + l) * NQ + q) * 3 + 0];
            const float theta = w[((gsel * L + l) * NQ + q) * 3 + 1];
            const float omega = w[((gsel * L + l) * NQ + q) * 3 + 2];
            const float c = cosf(0.5f * theta);
            const float s = sinf(0.5f * theta);
            float epx, epy, emx, emy;
            sincosf(-0.5f * (phi + omega), &epy, &epx);  // ep
            sincosf(-0.5f * (phi - omega), &emy, &emx);  // em
            gm[tid][0] = epx * c;   gm[tid][1] = epy * c;     // m00
            gm[tid][2] = -emx * s;  gm[tid][3] = emy * s;     // m01
            gm[tid][4] = emx * s;   gm[tid][5] = emy * s;     // m10
            gm[tid][6] = epx * c;   gm[tid][7] = -epy * c;    // m11
        }
        #pragma unroll
        for (int i = pbase; i < DIM; i += 4)
            S[col][i] = make_float2(i == col ? 1.0f : 0.0f, 0.0f);
        __syncthreads();

        float2* a = S[col];
        for (int l = 0; l < L; ++l) {
            for (int q = 0; q < NQ; ++q) {
                const float* m = gm[l * NQ + q];
                const int msk = 1 << (4 - q);
                #pragma unroll
                for (int k = 0; k < 4; ++k) {
                    const int p  = pbase + 4 * k;
                    const int lo = p & (msk - 1);
                    const int i0 = ((p & ~(msk - 1)) << 1) | lo;
                    const int i1 = i0 | msk;
                    const float2 a0 = a[i0], a1 = a[i1];
                    float2 n0, n1;
                    n0.x = m[0] * a0.x - m[1] * a0.y + m[2] * a1.x - m[3] * a1.y;
                    n0.y = m[0] * a0.y + m[1] * a0.x + m[2] * a1.y + m[3] * a1.x;
                    n1.x = m[4] * a0.x - m[5] * a0.y + m[6] * a1.x - m[7] * a1.y;
                    n1.y = m[4] * a0.y + m[5] * a0.x + m[6] * a1.y + m[7] * a1.x;
                    a[i0] = n0;
                    a[i1] = n1;
                }
                __syncwarp();
            }
            const int r = (l % (NQ - 1)) + 1;
            for (int q = 0; q < NQ; ++q) {
                const int cm = 1 << (4 - q);
                const int tq = (q + r) % NQ;
                const int tm = 1 << (4 - tq);
                #pragma unroll
                for (int k = 0; k < 4; ++k) {
                    const int p  = pbase + 4 * k;
                    const int lo = p & (tm - 1);
                    const int i0 = ((p & ~(tm - 1)) << 1) | lo;  // target bit 0
                    if (i0 & cm) {
                        const int i1 = i0 | tm;
                        const float2 tmp = a[i0];
                        a[i0] = a[i1];
                        a[i1] = tmp;
                    }
                }
                __syncwarp();
            }
        }

        #pragma unroll
        for (int k = 0; k < 4; ++k) {
            const int p = pbase + 4 * k;   // 0..15
            const int h  = p >> 3;
            const int i7 = p & 7;
            g_W[gsel][col][h * 16 + i7]     = a[p].x;
            g_W[gsel][col][h * 16 + 8 + i7] = a[p].y;
        }
        __threadfence();
        __syncthreads();
        if (tid == 0) atomicAdd((unsigned*)&g_done[gsel], 1u);   // release epoch
    }

    // =======================================================================
    // Consumer path (all blocks, incl. tile 0 which just built its own W).
    // =======================================================================
    const int h   = tid & 1;          // column half
    const int idx = tid >> 1;         // 0..63
    const int b0r = tile * 128 + idx;
    const int b1r = b0r + 64;
    const int b0 = min(b0r, B - 1);
    const int b1 = min(b1r, B - 1);

    // ---- prologue: packed (elem0, elem1) product-state prefix (overlaps build)
    ull p3p[8], c3p, s3p, c4p, s4p;
    {
        float cc0[NQ], ss0[NQ], cc1[NQ], ss1[NQ];
        #pragma unroll
        for (int q = 0; q < NQ; ++q) {
            __sincosf(0.5f * x[b0 * NQ + q], &ss0[q], &cc0[q]);
            __sincosf(0.5f * x[b1 * NQ + q], &ss1[q], &cc1[q]);
        }
        ull f0c = packab(cc0[0], cc1[0]), f0s = packab(ss0[0], ss1[0]);
        ull f1c = packab(cc0[1], cc1[1]), f1s = packab(ss0[1], ss1[1]);
        ull f2c = packab(cc0[2], cc1[2]), f2s = packab(ss0[2], ss1[2]);
        c3p = packab(cc0[3], cc1[3]);  s3p = packab(ss0[3], ss1[3]);
        c4p = packab(cc0[4], cc1[4]);  s4p = packab(ss0[4], ss1[4]);
        ull p2p[4];
        p2p[0] = fmul2(f0c, f1c); p2p[1] = fmul2(f0c, f1s);
        p2p[2] = fmul2(f0s, f1c); p2p[3] = fmul2(f0s, f1s);
        #pragma unroll
        for (int k = 0; k < 4; ++k) {
            p3p[2 * k + 0] = fmul2(p2p[k], f2c);
            p3p[2 * k + 1] = fmul2(p2p[k], f2s);
        }
    }

    // ---- wait for this generator's W (volatile-load spin; replay-safe) ----
    if (tile != 0) {
        if (tid == 0) {
            const unsigned consumers = (gridDim.x >> 2) - 1u;  // per gsel per exec
            const unsigned t = atomicAdd(&g_tick[gsel], 1u);   // one RMW per block
            const unsigned r = t / consumers;                  // execution index
            while (g_done[gsel] <= r) __nanosleep(128);        // plain L2 loads
            __threadfence();                                   // acquire
        }
        __syncthreads();
    }
    // stage W: 4 KB = 256 float4; 128 threads -> 2 each
    {
        const float4* src = reinterpret_cast<const float4*>(&g_W[gsel][0][0]);
        float4* dst = reinterpret_cast<float4*>(&Wsh[0][0]);
        dst[tid]       = src[tid];
        dst[tid + 128] = src[tid + 128];
    }
    __syncthreads();

    // ---- GEMM: acc[k] packs cols (2k,2k+1) of this half; k<4 Re, k>=4 Im ----
    ull a0[8], a1[8];
    #pragma unroll
    for (int k = 0; k < 8; ++k) { a0[k] = 0ULL; a1[k] = 0ULL; }

    const int hoff = h * 16;

    #pragma unroll
    for (int j4 = 0; j4 < 16; ++j4) {
        const ull p4p = fmul2(p3p[j4 >> 1], (j4 & 1) ? s3p : c3p);
        const float2 vA = unpack2(fmul2(p4p, c4p));
        const float2 vB = unpack2(fmul2(p4p, s4p));
        const ull sA0 = pack2(vA.x), sA1 = pack2(vA.y);
        const ull sB0 = pack2(vB.x), sB1 = pack2(vB.y);
        const ulonglong2* rA = reinterpret_cast<const ulonglong2*>(&Wsh[2 * j4][hoff]);
        const ulonglong2* rB = reinterpret_cast<const ulonglong2*>(&Wsh[2 * j4 + 1][hoff]);
        {
            const ulonglong2 w0 = rA[0], w1 = rA[1], w2 = rA[2], w3 = rA[3];
            a0[0] = ffma2(w0.x, sA0, a0[0]); a0[1] = ffma2(w0.y, sA0, a0[1]);
            a0[2] = ffma2(w1.x, sA0, a0[2]); a0[3] = ffma2(w1.y, sA0, a0[3]);
            a0[4] = ffma2(w2.x, sA0, a0[4]); a0[5] = ffma2(w2.y, sA0, a0[5]);
            a0[6] = ffma2(w3.x, sA0, a0[6]); a0[7] = ffma2(w3.y, sA0, a0[7]);
            a1[0] = ffma2(w0.x, sA1, a1[0]); a1[1] = ffma2(w0.y, sA1, a1[1]);
            a1[2] = ffma2(w1.x, sA1, a1[2]); a1[3] = ffma2(w1.y, sA1, a1[3]);
            a1[4] = ffma2(w2.x, sA1, a1[4]); a1[5] = ffma2(w2.y, sA1, a1[5]);
            a1[6] = ffma2(w3.x, sA1, a1[6]); a1[7] = ffma2(w3.y, sA1, a1[7]);
        }
        {
            const ulonglong2 w0 = rB[0], w1 = rB[1], w2 = rB[2], w3 = rB[3];
            a0[0] = ffma2(w0.x, sB0, a0[0]); a0[1] = ffma2(w0.y, sB0, a0[1]);
            a0[2] = ffma2(w1.x, sB0, a0[2]); a0[3] = ffma2(w1.y, sB0, a0[3]);
            a0[4] = ffma2(w2.x, sB0, a0[4]); a0[5] = ffma2(w2.y, sB0, a0[5]);
            a0[6] = ffma2(w3.x, sB0, a0[6]); a0[7] = ffma2(w3.y, sB0, a0[7]);
            a1[0] = ffma2(w0.x, sB1, a1[0]); a1[1] = ffma2(w0.y, sB1, a1[1]);
            a1[2] = ffma2(w1.x, sB1, a1[2]); a1[3] = ffma2(w1.y, sB1, a1[3]);
            a1[4] = ffma2(w2.x, sB1, a1[4]); a1[5] = ffma2(w2.y, sB1, a1[5]);
            a1[6] = ffma2(w3.x, sB1, a1[6]); a1[7] = ffma2(w3.y, sB1, a1[7]);
        }
    }

    // ---- epilogue: outputs 8h..8h+7 per element; max via shfl.xor(1) ----
    #pragma unroll
    for (int e = 0; e < 2; ++e) {
        const ull* a = e ? a1 : a0;
        const int br = e ? b1r : b0r;
        float pr[8];
        float mx = 0.0f;
        #pragma unroll
        for (int k = 0; k < 4; ++k) {
            const float2 re = unpack2(a[k]);
            const float2 im = unpack2(a[4 + k]);
            pr[2 * k + 0] = re.x * re.x + im.x * im.x;
            pr[2 * k + 1] = re.y * re.y + im.y * im.y;
            mx = fmaxf(mx, fmaxf(pr[2 * k], pr[2 * k + 1]));
        }
        mx = fmaxf(mx, __shfl_xor_sync(0xffffffffu, mx, 1));
        const float inv = 1.0f / mx;
        if (br < B) {
            float4* ov = reinterpret_cast<float4*>(out + (size_t)br * (G * NOUT) + gsel * NOUT + 8 * h);
            #pragma unroll
            for (int i4 = 0; i4 < 2; ++i4) {
                float4 o;
                o.x = pr[i4 * 4 + 0] * inv;
                o.y = pr[i4 * 4 + 1] * inv;
                o.z = pr[i4 * 4 + 2] * inv;
                o.w = pr[i4 * 4 + 3] * inv;
                ov[i4] = o;
            }
        }
    }
}

extern "C" void kernel_launch(void* const* d_in, const int* in_sizes, int n_in,
                              void* d_out, int out_size) {
    const float* x = (const float*)d_in[0];        // [B, 5]
    const float* w = (const float*)d_in[1];        // [4, 4, 5, 3]
    float* out = (float*)d_out;                    // [B, 64]
    const int B = in_sizes[0] / NQ;

    const int tiles = (B + 127) / 128;             // 128 elements per tile
    qgen_fused_kernel<<<tiles * G, 128>>>(x, w, out, B);
}

// round 16
// speedup vs baseline: 1.2261x; 1.1635x over previous
#include <cuda_runtime.h>
#include <cuda_bf16.h>
#include <math.h>

// ---------------------------------------------------------------------------
// PatchQuantumGenerator: 5 qubits, 1 ancilla, 4 StronglyEntanglingLayers,
// 4 generators.
//   * circuit after RY-embedding = fixed 32x32 unitary U_g per generator
//   * embedded state is a real product state s[j]
//   * p0/max(p0) == probs[:16]/max(probs[:16])  (sum normalization cancels)
// => out[b, g*16+i] = |y_i|^2 / max_i |y_i|^2,  y = U_g[0:16,:] @ s(b)
// Two kernels + PDL (R12 proven config); main kernel widened to 256-thread
// blocks / 256-elem tiles (same per-thread math, fewer blocks, shared Wsh).
// ---------------------------------------------------------------------------

#define NQ 5
#define DIM 32
#define NOUT 16
#define G 4
#define L 4
#define NGATES (L * NQ)

// W layout per row j: [Re(0..7), Im(0..7), Re(8..15), Im(8..15)]
// -> half h occupies floats [16h, 16h+16): its 8 Re then its 8 Im.
__device__ float g_W[G][DIM][2 * NOUT];

typedef unsigned long long ull;

__device__ __forceinline__ ull ffma2(ull a, ull b, ull c) {
    ull d;
    asm("fma.rn.f32x2 %0, %1, %2, %3;" : "=l"(d) : "l"(a), "l"(b), "l"(c));
    return d;
}
__device__ __forceinline__ ull fmul2(ull a, ull b) {
    ull d;
    asm("mul.rn.f32x2 %0, %1, %2;" : "=l"(d) : "l"(a), "l"(b));
    return d;
}
__device__ __forceinline__ ull packab(float lo, float hi) {
    ull r;
    asm("mov.b64 %0, {%1, %2};" : "=l"(r) : "f"(lo), "f"(hi));
    return r;
}
__device__ __forceinline__ ull pack2(float x) {
    ull r;
    asm("mov.b64 %0, {%1, %1};" : "=l"(r) : "f"(x));
    return r;
}
__device__ __forceinline__ float2 unpack2(ull a) {
    float lo, hi;
    asm("mov.b64 {%0, %1}, %2;" : "=f"(lo), "=f"(hi) : "l"(a));
    return make_float2(lo, hi);
}

// ---------------------------------------------------------------------------
// Kernel A: build the 4 unitaries. One block per generator, 512 threads:
// thread = (col = t>>4, p = t&15); per-gate sync is warp-local.
// Ends with a PDL trigger so kernel B can launch while A drains.
// ---------------------------------------------------------------------------
__global__ void __launch_bounds__(512, 1)
build_unitaries_kernel(const float* __restrict__ w) {
    __shared__ float2 S[DIM][DIM];        // [column][amplitude], 8KB
    __shared__ float gm[NGATES][8];       // gate matrices

    const int g   = blockIdx.x;
    const int t   = threadIdx.x;          // 0..511
    const int col = t >> 4;               // 0..31
    const int p   = t & 15;               // pair index 0..15

    if (t < NGATES) {
        const int l = t / NQ, q = t % NQ;
        const float phi   = w[((g * L + l) * NQ + q) * 3 + 0];
        const float theta = w[((g * L + l) * NQ + q) * 3 + 1];
        const float omega = w[((g * L + l) * NQ + q) * 3 + 2];
        const float c = cosf(0.5f * theta);
        const float s = sinf(0.5f * theta);
        float epx, epy, emx, emy;
        sincosf(-0.5f * (phi + omega), &epy, &epx);   // ep = e^{-i(phi+omega)/2}
        sincosf(-0.5f * (phi - omega), &emy, &emx);   // em = e^{-i(phi-omega)/2}
        // m00 = ep*c ; m01 = -conj(em)*s ; m10 = em*s ; m11 = conj(ep)*c
        gm[t][0] = epx * c;   gm[t][1] = epy * c;
        gm[t][2] = -emx * s;  gm[t][3] = emy * s;
        gm[t][4] = emx * s;   gm[t][5] = emy * s;
        gm[t][6] = epx * c;   gm[t][7] = -epy * c;
    }

    S[col][p]      = make_float2(col == p      ? 1.0f : 0.0f, 0.0f);
    S[col][p + 16] = make_float2(col == p + 16 ? 1.0f : 0.0f, 0.0f);
    __syncthreads();

    float2* a = S[col];

    for (int l = 0; l < L; ++l) {
        for (int q = 0; q < NQ; ++q) {
            const float* m = gm[l * NQ + q];
            const int msk = 1 << (4 - q);
            const int lo  = p & (msk - 1);
            const int i0  = ((p & ~(msk - 1)) << 1) | lo;
            const int i1  = i0 | msk;
            const float2 a0 = a[i0], a1 = a[i1];
            float2 n0, n1;
            n0.x = m[0] * a0.x - m[1] * a0.y + m[2] * a1.x - m[3] * a1.y;
            n0.y = m[0] * a0.y + m[1] * a0.x + m[2] * a1.y + m[3] * a1.x;
            n1.x = m[4] * a0.x - m[5] * a0.y + m[6] * a1.x - m[7] * a1.y;
            n1.y = m[4] * a0.y + m[5] * a0.x + m[6] * a1.y + m[7] * a1.x;
            a[i0] = n0;
            a[i1] = n1;
            __syncwarp();
        }
        const int r = (l % (NQ - 1)) + 1;
        for (int q = 0; q < NQ; ++q) {
            const int cm = 1 << (4 - q);
            const int tq = (q + r) % NQ;
            const int tm = 1 << (4 - tq);
            const int lo = p & (tm - 1);
            const int i0 = ((p & ~(tm - 1)) << 1) | lo;   // target bit = 0
            if (i0 & cm) {
                const int i1 = i0 | tm;
                const float2 tmp = a[i0];
                a[i0] = a[i1];
                a[i1] = tmp;
            }
            __syncwarp();
        }
    }

    // output i = p: Re -> (i>>3)*16 + (i&7), Im -> +8
    const int h  = p >> 3;
    const int i7 = p & 7;
    g_W[g][col][h * 16 + i7]     = a[p].x;
    g_W[g][col][h * 16 + 8 + i7] = a[p].y;

    __threadfence();
#if __CUDA_ARCH__ >= 900
    cudaTriggerProgrammaticLaunchCompletion();
#endif
}

// ---------------------------------------------------------------------------
// Kernel B: block = (tile of 256 batch elems) x (one g). 256 threads.
// Thread = (idx = tid>>1 -> elems b0, b0+128 ; h = tid&1 -> col half).
// Prologue runs BEFORE the PDL grid dependency sync.
// ---------------------------------------------------------------------------
__global__ void __launch_bounds__(256, 3)
qgen_main_kernel(const float* __restrict__ x, float* __restrict__ out, int B) {
    __shared__ float Wsh[DIM][2 * NOUT];   // 4 KB
    const int gsel = blockIdx.x & 3;
    const int tile = blockIdx.x >> 2;

    const int h   = threadIdx.x & 1;       // column half
    const int idx = threadIdx.x >> 1;      // 0..127
    const int b0r = tile * 256 + idx;
    const int b1r = b0r + 128;
    // clamp for the (never-taken in practice) tail; all threads stay alive
    const int b0 = min(b0r, B - 1);
    const int b1 = min(b1r, B - 1);

    // ---- prologue: packed (elem0, elem1) product-state prefix ----
    ull p3p[8], c3p, s3p, c4p, s4p;
    {
        float cc0[NQ], ss0[NQ], cc1[NQ], ss1[NQ];
        #pragma unroll
        for (int q = 0; q < NQ; ++q) {
            __sincosf(0.5f * x[b0 * NQ + q], &ss0[q], &cc0[q]);
            __sincosf(0.5f * x[b1 * NQ + q], &ss1[q], &cc1[q]);
        }
        ull f0c = packab(cc0[0], cc1[0]), f0s = packab(ss0[0], ss1[0]);
        ull f1c = packab(cc0[1], cc1[1]), f1s = packab(ss0[1], ss1[1]);
        ull f2c = packab(cc0[2], cc1[2]), f2s = packab(ss0[2], ss1[2]);
        c3p = packab(cc0[3], cc1[3]);  s3p = packab(ss0[3], ss1[3]);
        c4p = packab(cc0[4], cc1[4]);  s4p = packab(ss0[4], ss1[4]);
        ull p2p[4];
        p2p[0] = fmul2(f0c, f1c); p2p[1] = fmul2(f0c, f1s);
        p2p[2] = fmul2(f0s, f1c); p2p[3] = fmul2(f0s, f1s);
        #pragma unroll
        for (int k = 0; k < 4; ++k) {
            p3p[2 * k + 0] = fmul2(p2p[k], f2c);
            p3p[2 * k + 1] = fmul2(p2p[k], f2s);
        }
    }

    // ---- wait for kernel A's g_W, then stage it (all 256 threads) ----
#if __CUDA_ARCH__ >= 900
    cudaGridDependencySynchronize();
#endif
    {
        // 4 KB = 256 float4; 256 threads -> 1 each
        const float4* src = reinterpret_cast<const float4*>(&g_W[gsel][0][0]);
        float4* dst = reinterpret_cast<float4*>(&Wsh[0][0]);
        dst[threadIdx.x] = src[threadIdx.x];
    }
    __syncthreads();

    // ---- GEMM: acc[k] packs cols (2k,2k+1) of this half; k<4 Re, k>=4 Im ----
    ull a0[8], a1[8];
    #pragma unroll
    for (int k = 0; k < 8; ++k) { a0[k] = 0ULL; a1[k] = 0ULL; }

    const int hoff = h * 16;

    #pragma unroll
    for (int j4 = 0; j4 < 16; ++j4) {
        const ull p4p = fmul2(p3p[j4 >> 1], (j4 & 1) ? s3p : c3p);
        const float2 vA = unpack2(fmul2(p4p, c4p));
        const float2 vB = unpack2(fmul2(p4p, s4p));
        const ull sA0 = pack2(vA.x), sA1 = pack2(vA.y);
        const ull sB0 = pack2(vB.x), sB1 = pack2(vB.y);
        const ulonglong2* rA = reinterpret_cast<const ulonglong2*>(&Wsh[2 * j4][hoff]);
        const ulonglong2* rB = reinterpret_cast<const ulonglong2*>(&Wsh[2 * j4 + 1][hoff]);
        {
            const ulonglong2 w0 = rA[0], w1 = rA[1], w2 = rA[2], w3 = rA[3];
            a0[0] = ffma2(w0.x, sA0, a0[0]); a0[1] = ffma2(w0.y, sA0, a0[1]);
            a0[2] = ffma2(w1.x, sA0, a0[2]); a0[3] = ffma2(w1.y, sA0, a0[3]);
            a0[4] = ffma2(w2.x, sA0, a0[4]); a0[5] = ffma2(w2.y, sA0, a0[5]);
            a0[6] = ffma2(w3.x, sA0, a0[6]); a0[7] = ffma2(w3.y, sA0, a0[7]);
            a1[0] = ffma2(w0.x, sA1, a1[0]); a1[1] = ffma2(w0.y, sA1, a1[1]);
            a1[2] = ffma2(w1.x, sA1, a1[2]); a1[3] = ffma2(w1.y, sA1, a1[3]);
            a1[4] = ffma2(w2.x, sA1, a1[4]); a1[5] = ffma2(w2.y, sA1, a1[5]);
            a1[6] = ffma2(w3.x, sA1, a1[6]); a1[7] = ffma2(w3.y, sA1, a1[7]);
        }
        {
            const ulonglong2 w0 = rB[0], w1 = rB[1], w2 = rB[2], w3 = rB[3];
            a0[0] = ffma2(w0.x, sB0, a0[0]); a0[1] = ffma2(w0.y, sB0, a0[1]);
            a0[2] = ffma2(w1.x, sB0, a0[2]); a0[3] = ffma2(w1.y, sB0, a0[3]);
            a0[4] = ffma2(w2.x, sB0, a0[4]); a0[5] = ffma2(w2.y, sB0, a0[5]);
            a0[6] = ffma2(w3.x, sB0, a0[6]); a0[7] = ffma2(w3.y, sB0, a0[7]);
            a1[0] = ffma2(w0.x, sB1, a1[0]); a1[1] = ffma2(w0.y, sB1, a1[1]);
            a1[2] = ffma2(w1.x, sB1, a1[2]); a1[3] = ffma2(w1.y, sB1, a1[3]);
            a1[4] = ffma2(w2.x, sB1, a1[4]); a1[5] = ffma2(w2.y, sB1, a1[5]);
            a1[6] = ffma2(w3.x, sB1, a1[6]); a1[7] = ffma2(w3.y, sB1, a1[7]);
        }
    }

    // ---- epilogue: outputs 8h..8h+7 per element; max via shfl.xor(1) ----
    #pragma unroll
    for (int e = 0; e < 2; ++e) {
        const ull* a = e ? a1 : a0;
        const int br = e ? b1r : b0r;
        float pr[8];
        float mx = 0.0f;
        #pragma unroll
        for (int k = 0; k < 4; ++k) {
            const float2 re = unpack2(a[k]);       // outputs 8h+2k, 8h+2k+1
            const float2 im = unpack2(a[4 + k]);
            pr[2 * k + 0] = re.x * re.x + im.x * im.x;
            pr[2 * k + 1] = re.y * re.y + im.y * im.y;
            mx = fmaxf(mx, fmaxf(pr[2 * k], pr[2 * k + 1]));
        }
        mx = fmaxf(mx, __shfl_xor_sync(0xffffffffu, mx, 1));
        const float inv = 1.0f / mx;
        if (br < B) {
            float4* ov = reinterpret_cast<float4*>(out + (size_t)br * (G * NOUT) + gsel * NOUT + 8 * h);
            #pragma unroll
            for (int i4 = 0; i4 < 2; ++i4) {
                float4 o;
                o.x = pr[i4 * 4 + 0] * inv;
                o.y = pr[i4 * 4 + 1] * inv;
                o.z = pr[i4 * 4 + 2] * inv;
                o.w = pr[i4 * 4 + 3] * inv;
                ov[i4] = o;
            }
        }
    }
}

extern "C" void kernel_launch(void* const* d_in, const int* in_sizes, int n_in,
                              void* d_out, int out_size) {
    const float* x = (const float*)d_in[0];        // [B, 5]
    const float* w = (const float*)d_in[1];        // [4, 4, 5, 3]
    float* out = (float*)d_out;                    // [B, 64]
    const int B = in_sizes[0] / NQ;

    build_unitaries_kernel<<<G, 512>>>(w);

    const int tiles = (B + 255) / 256;             // 256 elements per tile

    cudaLaunchConfig_t cfg = {};
    cfg.gridDim  = dim3(tiles * G);
    cfg.blockDim = dim3(256);
    cfg.dynamicSmemBytes = 0;
    cfg.stream = 0;
    cudaLaunchAttribute attr[1];
    attr[0].id = cudaLaunchAttributeProgrammaticStreamSerialization;
    attr[0].val.programmaticStreamSerializationAllowed = 1;
    cfg.attrs = attr;
    cfg.numAttrs = 1;
    cudaLaunchKernelEx(&cfg, qgen_main_kernel, x, out, B);
}

// round 17
// speedup vs baseline: 1.2371x; 1.0090x over previous
#include <cuda_runtime.h>
#include <cuda_bf16.h>
#include <math.h>

// ---------------------------------------------------------------------------
// PatchQuantumGenerator — single fused kernel, fast shfl builder.
//   * circuit after RY-embedding = fixed 32x32 unitary U_g per generator
//   * embedded state is a real product state s[j]
//   * p0/max(p0) == probs[:16]/max(probs[:16])
// => out[b, g*16+i] = |y_i|^2 / max_i |y_i|^2,  y = U_g[0:16,:] @ s(b)
//
// Block (gsel, tile): tile==0 (blocks 0..3, wave 1) builds U_gsel with a
// register/shfl builder: warp w handles columns 4w..4w+3, lane l holds
// amplitude l of each column. Rot = 2 shfl.xor + cmul per column (no smem,
// no syncs in the chain); CNOT = lane permutation shfl. ~1.5-2us.
// Other tiles: prologue first (overlaps build), then spin on the proven
// monotonic epoch flag (R14/R15 correctness-passed, graph-replay safe).
// GEMM body = R16 proven: f32x2 FMA, 2 elems/thread, h=2 column split.
// ---------------------------------------------------------------------------

#define NQ 5
#define DIM 32
#define NOUT 16
#define G 4
#define L 4
#define NGATES (L * NQ)

// W layout per row j: [Re(0..7), Im(0..7), Re(8..15), Im(8..15)]
__device__ float g_W[G][DIM][2 * NOUT];
__device__ volatile unsigned g_done[G];  // monotonic: +1 per generator per execution
__device__ unsigned g_tick[G];           // monotonic consumer tickets

typedef unsigned long long ull;

__device__ __forceinline__ ull ffma2(ull a, ull b, ull c) {
    ull d;
    asm("fma.rn.f32x2 %0, %1, %2, %3;" : "=l"(d) : "l"(a), "l"(b), "l"(c));
    return d;
}
__device__ __forceinline__ ull fmul2(ull a, ull b) {
    ull d;
    asm("mul.rn.f32x2 %0, %1, %2;" : "=l"(d) : "l"(a), "l"(b));
    return d;
}
__device__ __forceinline__ ull packab(float lo, float hi) {
    ull r;
    asm("mov.b64 %0, {%1, %2};" : "=l"(r) : "f"(lo), "f"(hi));
    return r;
}
__device__ __forceinline__ ull pack2(float x) {
    ull r;
    asm("mov.b64 %0, {%1, %1};" : "=l"(r) : "f"(x));
    return r;
}
__device__ __forceinline__ float2 unpack2(ull a) {
    float lo, hi;
    asm("mov.b64 {%0, %1}, %2;" : "=f"(lo), "=f"(hi) : "l"(a));
    return make_float2(lo, hi);
}

__global__ void __launch_bounds__(256, 3)
qgen_fused_kernel(const float* __restrict__ x, const float* __restrict__ w,
                  float* __restrict__ out, int B) {
    __shared__ float gm[NGATES][8];       // builder gate matrices (tile 0 only)
    __shared__ float Wsh[DIM][2 * NOUT];  // 4 KB GEMM operand

    const int gsel = blockIdx.x & 3;
    const int tile = blockIdx.x >> 2;
    const int tid  = threadIdx.x;

    // =======================================================================
    // Builder: tile 0, 8 warps; warp wrp -> columns 4*wrp..4*wrp+3,
    // lane l holds amplitude index l of each column (in registers).
    // =======================================================================
    if (tile == 0) {
        const int wrp  = tid >> 5;       // 0..7
        const int lane = tid & 31;

        if (tid < NGATES) {
            const int l = tid / NQ, q = tid % NQ;
            const float phi   = w[((gsel * L + l) * NQ + q) * 3 + 0];
            const float theta = w[((gsel * L + l) * NQ + q) * 3 + 1];
            const float omega = w[((gsel * L + l) * NQ + q) * 3 + 2];
            const float c = cosf(0.5f * theta);
            const float s = sinf(0.5f * theta);
            float epx, epy, emx, emy;
            sincosf(-0.5f * (phi + omega), &epy, &epx);  // ep
            sincosf(-0.5f * (phi - omega), &emy, &emx);  // em
            gm[tid][0] = epx * c;   gm[tid][1] = epy * c;     // m00
            gm[tid][2] = -emx * s;  gm[tid][3] = emy * s;     // m01
            gm[tid][4] = emx * s;   gm[tid][5] = emy * s;     // m10
            gm[tid][6] = epx * c;   gm[tid][7] = -epy * c;    // m11
        }

        float are[4], aim[4];
        #pragma unroll
        for (int j = 0; j < 4; ++j) {
            are[j] = (lane == wrp * 4 + j) ? 1.0f : 0.0f;
            aim[j] = 0.0f;
        }
        __syncthreads();   // gm ready

        for (int l = 0; l < L; ++l) {
            // 5 Rot gates (qubit 0 = MSB of index)
            #pragma unroll
            for (int q = 0; q < NQ; ++q) {
                const float* m = gm[l * NQ + q];
                const int msk = 1 << (4 - q);
                const bool b = (lane & msk) != 0;
                // own coeff = b ? m11 : m00 ; partner coeff = b ? m10 : m01
                const float cAr = b ? m[6] : m[0];
                const float cAi = b ? m[7] : m[1];
                const float cBr = b ? m[4] : m[2];
                const float cBi = b ? m[5] : m[3];
                #pragma unroll
                for (int j = 0; j < 4; ++j) {
                    const float pre = __shfl_xor_sync(0xffffffffu, are[j], msk);
                    const float pim = __shfl_xor_sync(0xffffffffu, aim[j], msk);
                    const float nr = cAr * are[j] - cAi * aim[j] + cBr * pre - cBi * pim;
                    const float ni = cAr * aim[j] + cAi * are[j] + cBr * pim + cBi * pre;
                    are[j] = nr;
                    aim[j] = ni;
                }
            }
            // 5 CNOTs: new_a[i] = a[i ^ tm] if (i & cm) else a[i]
            const int r = (l % (NQ - 1)) + 1;
            #pragma unroll
            for (int q = 0; q < NQ; ++q) {
                const int cm = 1 << (4 - q);
                const int tq = (q + r) % NQ;
                const int tm = 1 << (4 - tq);
                const int src = (lane & cm) ? (lane ^ tm) : lane;
                #pragma unroll
                for (int j = 0; j < 4; ++j) {
                    are[j] = __shfl_sync(0xffffffffu, are[j], src);
                    aim[j] = __shfl_sync(0xffffffffu, aim[j], src);
                }
            }
        }

        // rows 0..15 feed the output; layout: Re -> (i>>3)*16+(i&7), Im -> +8
        if (lane < 16) {
            const int h  = lane >> 3;
            const int i7 = lane & 7;
            #pragma unroll
            for (int j = 0; j < 4; ++j) {
                const int col = wrp * 4 + j;
                g_W[gsel][col][h * 16 + i7]     = are[j];
                g_W[gsel][col][h * 16 + 8 + i7] = aim[j];
            }
        }
        __threadfence();
        __syncthreads();
        if (tid == 0) atomicAdd((unsigned*)&g_done[gsel], 1u);   // release epoch
    }

    // =======================================================================
    // Consumer path (all blocks; tile 0 consumes its own fresh W).
    // =======================================================================
    const int h   = tid & 1;          // column half
    const int idx = tid >> 1;         // 0..127
    const int b0r = tile * 256 + idx;
    const int b1r = b0r + 128;
    const int b0 = min(b0r, B - 1);
    const int b1 = min(b1r, B - 1);

    // ---- prologue: packed (elem0, elem1) product-state prefix (overlaps build)
    ull p3p[8], c3p, s3p, c4p, s4p;
    {
        float cc0[NQ], ss0[NQ], cc1[NQ], ss1[NQ];
        #pragma unroll
        for (int q = 0; q < NQ; ++q) {
            __sincosf(0.5f * x[b0 * NQ + q], &ss0[q], &cc0[q]);
            __sincosf(0.5f * x[b1 * NQ + q], &ss1[q], &cc1[q]);
        }
        ull f0c = packab(cc0[0], cc1[0]), f0s = packab(ss0[0], ss1[0]);
        ull f1c = packab(cc0[1], cc1[1]), f1s = packab(ss0[1], ss1[1]);
        ull f2c = packab(cc0[2], cc1[2]), f2s = packab(ss0[2], ss1[2]);
        c3p = packab(cc0[3], cc1[3]);  s3p = packab(ss0[3], ss1[3]);
        c4p = packab(cc0[4], cc1[4]);  s4p = packab(ss0[4], ss1[4]);
        ull p2p[4];
        p2p[0] = fmul2(f0c, f1c); p2p[1] = fmul2(f0c, f1s);
        p2p[2] = fmul2(f0s, f1c); p2p[3] = fmul2(f0s, f1s);
        #pragma unroll
        for (int k = 0; k < 4; ++k) {
            p3p[2 * k + 0] = fmul2(p2p[k], f2c);
            p3p[2 * k + 1] = fmul2(p2p[k], f2s);
        }
    }

    // ---- wait for this generator's W (epoch flag; replay-safe) ----
    if (tile != 0) {
        if (tid == 0) {
            const unsigned consumers = (gridDim.x >> 2) - 1u;  // per gsel per exec
            const unsigned t = atomicAdd(&g_tick[gsel], 1u);   // one RMW per block
            const unsigned r = t / consumers;                  // execution index
            while (g_done[gsel] <= r) __nanosleep(64);         // plain L2 loads
            __threadfence();                                   // acquire
        }
        __syncthreads();
    }
    // stage W: 4 KB = 256 float4; 256 threads -> 1 each
    {
        const float4* src = reinterpret_cast<const float4*>(&g_W[gsel][0][0]);
        float4* dst = reinterpret_cast<float4*>(&Wsh[0][0]);
        dst[tid] = src[tid];
    }
    __syncthreads();

    // ---- GEMM: acc[k] packs cols (2k,2k+1) of this half; k<4 Re, k>=4 Im ----
    ull a0[8], a1[8];
    #pragma unroll
    for (int k = 0; k < 8; ++k) { a0[k] = 0ULL; a1[k] = 0ULL; }

    const int hoff = h * 16;

    #pragma unroll
    for (int j4 = 0; j4 < 16; ++j4) {
        const ull p4p = fmul2(p3p[j4 >> 1], (j4 & 1) ? s3p : c3p);
        const float2 vA = unpack2(fmul2(p4p, c4p));
        const float2 vB = unpack2(fmul2(p4p, s4p));
        const ull sA0 = pack2(vA.x), sA1 = pack2(vA.y);
        const ull sB0 = pack2(vB.x), sB1 = pack2(vB.y);
        const ulonglong2* rA = reinterpret_cast<const ulonglong2*>(&Wsh[2 * j4][hoff]);
        const ulonglong2* rB = reinterpret_cast<const ulonglong2*>(&Wsh[2 * j4 + 1][hoff]);
        {
            const ulonglong2 w0 = rA[0], w1 = rA[1], w2 = rA[2], w3 = rA[3];
            a0[0] = ffma2(w0.x, sA0, a0[0]); a0[1] = ffma2(w0.y, sA0, a0[1]);
            a0[2] = ffma2(w1.x, sA0, a0[2]); a0[3] = ffma2(w1.y, sA0, a0[3]);
            a0[4] = ffma2(w2.x, sA0, a0[4]); a0[5] = ffma2(w2.y, sA0, a0[5]);
            a0[6] = ffma2(w3.x, sA0, a0[6]); a0[7] = ffma2(w3.y, sA0, a0[7]);
            a1[0] = ffma2(w0.x, sA1, a1[0]); a1[1] = ffma2(w0.y, sA1, a1[1]);
            a1[2] = ffma2(w1.x, sA1, a1[2]); a1[3] = ffma2(w1.y, sA1, a1[3]);
            a1[4] = ffma2(w2.x, sA1, a1[4]); a1[5] = ffma2(w2.y, sA1, a1[5]);
            a1[6] = ffma2(w3.x, sA1, a1[6]); a1[7] = ffma2(w3.y, sA1, a1[7]);
        }
        {
            const ulonglong2 w0 = rB[0], w1 = rB[1], w2 = rB[2], w3 = rB[3];
            a0[0] = ffma2(w0.x, sB0, a0[0]); a0[1] = ffma2(w0.y, sB0, a0[1]);
            a0[2] = ffma2(w1.x, sB0, a0[2]); a0[3] = ffma2(w1.y, sB0, a0[3]);
            a0[4] = ffma2(w2.x, sB0, a0[4]); a0[5] = ffma2(w2.y, sB0, a0[5]);
            a0[6] = ffma2(w3.x, sB0, a0[6]); a0[7] = ffma2(w3.y, sB0, a0[7]);
            a1[0] = ffma2(w0.x, sB1, a1[0]); a1[1] = ffma2(w0.y, sB1, a1[1]);
            a1[2] = ffma2(w1.x, sB1, a1[2]); a1[3] = ffma2(w1.y, sB1, a1[3]);
            a1[4] = ffma2(w2.x, sB1, a1[4]); a1[5] = ffma2(w2.y, sB1, a1[5]);
            a1[6] = ffma2(w3.x, sB1, a1[6]); a1[7] = ffma2(w3.y, sB1, a1[7]);
        }
    }

    // ---- epilogue: outputs 8h..8h+7 per element; max via shfl.xor(1) ----
    #pragma unroll
    for (int e = 0; e < 2; ++e) {
        const ull* a = e ? a1 : a0;
        const int br = e ? b1r : b0r;
        float pr[8];
        float mx = 0.0f;
        #pragma unroll
        for (int k = 0; k < 4; ++k) {
            const float2 re = unpack2(a[k]);
            const float2 im = unpack2(a[4 + k]);
            pr[2 * k + 0] = re.x * re.x + im.x * im.x;
            pr[2 * k + 1] = re.y * re.y + im.y * im.y;
            mx = fmaxf(mx, fmaxf(pr[2 * k], pr[2 * k + 1]));
        }
        mx = fmaxf(mx, __shfl_xor_sync(0xffffffffu, mx, 1));
        const float inv = 1.0f / mx;
        if (br < B) {
            float4* ov = reinterpret_cast<float4*>(out + (size_t)br * (G * NOUT) + gsel * NOUT + 8 * h);
            #pragma unroll
            for (int i4 = 0; i4 < 2; ++i4) {
                float4 o;
                o.x = pr[i4 * 4 + 0] * inv;
                o.y = pr[i4 * 4 + 1] * inv;
                o.z = pr[i4 * 4 + 2] * inv;
                o.w = pr[i4 * 4 + 3] * inv;
                ov[i4] = o;
            }
        }
    }
}

extern "C" void kernel_launch(void* const* d_in, const int* in_sizes, int n_in,
                              void* d_out, int out_size) {
    const float* x = (const float*)d_in[0];        // [B, 5]
    const float* w = (const float*)d_in[1];        // [4, 4, 5, 3]
    float* out = (float*)d_out;                    // [B, 64]
    const int B = in_sizes[0] / NQ;

    const int tiles = (B + 255) / 256;             // 256 elements per tile
    qgen_fused_kernel<<<tiles * G, 256>>>(x, w, out, B);
}